// round 13
// baseline (speedup 1.0000x reference)
#include <cuda_runtime.h>
#include <cuda_bf16.h>

// Bicubic x4 upsample, Keys a=-0.5, matching jax.image.resize(method="cubic").
//   input (16,3,256,256) f32 -> output (16,3,1024,1024) f32
// Persistent-CTA variant of the R7 kernel: 888 CTAs (148 SM x 6) grid-stride
// over 3072 tiles of 32x32 input cells -> 128x128 output each. Per-tile body
// identical to R7 (staged 36x36 halo, fused rolling 5-deep h-window,
// streaming .cs float4 stores). Goal: continuous store stream across tile
// boundaries instead of wave-synchronized ramps.

#define IN_W   256
#define IN_H   256
#define OUT_W  1024
#define PLANE_IN  (IN_W * IN_H)
#define PLANE_OUT (OUT_W * OUT_W)
#define N_TILES   3072                 // 8 x 8 x 48

#define A0 (-0.0439453125f)
#define A1 ( 0.3896484375f)
#define A2 ( 0.7275390625f)
#define A3 (-0.0732421875f)
#define B0 (-0.0068359375f)
#define B1 ( 0.0908203125f)
#define B2 ( 0.9638671875f)
#define B3 (-0.0478515625f)

// streaming (evict-first) 128-bit store
__device__ __forceinline__ void stcs4(float* p, float4 v) {
    asm volatile("st.global.cs.v4.f32 [%0], {%1,%2,%3,%4};"
                 :: "l"(p), "f"(v.x), "f"(v.y), "f"(v.z), "f"(v.w) : "memory");
}

__device__ __forceinline__ float border_dot5(int q, const float wt[5],
                                             float v0, float v1, float v2,
                                             float v3, float v4)
{
    float w[5]; float s = 0.f;
#pragma unroll
    for (int j = 0; j < 5; j++) {
        int idx = q - 2 + j;
        float ww = (idx >= 0 && idx < IN_W) ? wt[j] : 0.f;
        w[j] = ww; s += ww;
    }
    float inv = 1.0f / s;
    float r = w[0] * v0;
    r = fmaf(w[1], v1, r);
    r = fmaf(w[2], v2, r);
    r = fmaf(w[3], v3, r);
    r = fmaf(w[4], v4, r);
    return r * inv;
}

__device__ __forceinline__ float4 border_dot5_v4(int q, const float wt[5],
                                                 float4 v0, float4 v1, float4 v2,
                                                 float4 v3, float4 v4)
{
    float w[5]; float s = 0.f;
#pragma unroll
    for (int j = 0; j < 5; j++) {
        int idx = q - 2 + j;
        float ww = (idx >= 0 && idx < IN_H) ? wt[j] : 0.f;
        w[j] = ww; s += ww;
    }
    float inv = 1.0f / s;
    float4 o;
    o.x = (fmaf(w[4], v4.x, fmaf(w[3], v3.x, fmaf(w[2], v2.x, fmaf(w[1], v1.x, w[0] * v0.x))))) * inv;
    o.y = (fmaf(w[4], v4.y, fmaf(w[3], v3.y, fmaf(w[2], v2.y, fmaf(w[1], v1.y, w[0] * v0.y))))) * inv;
    o.z = (fmaf(w[4], v4.z, fmaf(w[3], v3.z, fmaf(w[2], v2.z, fmaf(w[1], v1.z, w[0] * v0.z))))) * inv;
    o.w = (fmaf(w[4], v4.w, fmaf(w[3], v3.w, fmaf(w[2], v2.w, fmaf(w[1], v1.w, w[0] * v0.w))))) * inv;
    return o;
}

__global__ void __launch_bounds__(256, 6)
bicubic4x_persist_kernel(const float* __restrict__ in, float* __restrict__ out)
{
    __shared__ float sin_t[36][40];    // input halo only (5.76 KB)

    const int tid = threadIdx.x;

    static const float TA[5]  = {A0,  A1,  A2,  A3,  0.f};
    static const float TB[5]  = {B0,  B1,  B2,  B3,  0.f};
    static const float TBr[5] = {0.f, B3,  B2,  B1,  B0 };
    static const float TAr[5] = {0.f, A3,  A2,  A1,  A0 };

    // per-thread fixed roles (same for every tile)
    const int q  = tid & 31;           // x-cell column within tile
    const int ys = tid >> 5;           // 0..7 strip index
    const int rb = ys * 4;             // first halo row of this strip

    for (int t = blockIdx.x; t < N_TILES; t += gridDim.x) {
        const int bx    = t & 7;
        const int by    = (t >> 3) & 7;
        const int plane = t >> 6;

        const int qx0 = bx * 32;
        const int qy0 = by * 32;
        const bool xedge = (bx == 0) | (bx == 7);
        const bool yedge = (by == 0) | (by == 7);

        const float* ip = in + (size_t)plane * PLANE_IN;

        // ---------- stage 36x36 halo (coalesced, clamped) ----------
#pragma unroll
        for (int i = tid; i < 36 * 36; i += 256) {
            int r = i / 36;
            int c = i - r * 36;
            int gy = qy0 - 2 + r;  gy = gy < 0 ? 0 : (gy > IN_H - 1 ? IN_H - 1 : gy);
            int gx = qx0 - 2 + c;  gx = gx < 0 ? 0 : (gx > IN_W - 1 ? IN_W - 1 : gx);
            sin_t[r][c] = __ldg(ip + gy * IN_W + gx);
        }
        __syncthreads();

        // ---------- fused horizontal + vertical pass ----------
        const int qg = qx0 + q;
        const bool xint = !xedge || (qg >= 2 && qg <= IN_W - 3);

#define COMPUTE_H(dst, rr)                                                      \
        {                                                                       \
            const float* srow = sin_t[rr];                                      \
            float v0 = srow[q + 0], v1 = srow[q + 1], v2 = srow[q + 2],         \
                  v3 = srow[q + 3], v4 = srow[q + 4];                           \
            if (xint) {                                                         \
                dst.x = fmaf(A0, v0, fmaf(A1, v1, fmaf(A2, v2, A3 * v3)));      \
                dst.y = fmaf(B0, v0, fmaf(B1, v1, fmaf(B2, v2, B3 * v3)));      \
                dst.z = fmaf(B3, v1, fmaf(B2, v2, fmaf(B1, v3, B0 * v4)));      \
                dst.w = fmaf(A3, v1, fmaf(A2, v2, fmaf(A1, v3, A0 * v4)));      \
            } else {                                                            \
                dst.x = border_dot5(qg, TA,  v0, v1, v2, v3, v4);               \
                dst.y = border_dot5(qg, TB,  v0, v1, v2, v3, v4);               \
                dst.z = border_dot5(qg, TBr, v0, v1, v2, v3, v4);               \
                dst.w = border_dot5(qg, TAr, v0, v1, v2, v3, v4);               \
            }                                                                   \
        }

        float4 h0, h1, h2, h3, h4;
        COMPUTE_H(h0, rb + 0);
        COMPUTE_H(h1, rb + 1);
        COMPUTE_H(h2, rb + 2);
        COMPUTE_H(h3, rb + 3);
        COMPUTE_H(h4, rb + 4);

        float* op0 = out + (size_t)plane * PLANE_OUT
                         + (size_t)((qy0 + rb) * 4) * OUT_W
                         + (size_t)(qx0 * 4) + (size_t)q * 4;

#pragma unroll
        for (int c = 0; c < 4; c++) {
            const int qyg = qy0 + rb + c;
            float* op = op0 + (size_t)(c * 4) * OUT_W;

            if (!yedge || (qyg >= 2 && qyg <= IN_H - 3)) {
                float4 o;
                o.x = fmaf(A0, h0.x, fmaf(A1, h1.x, fmaf(A2, h2.x, A3 * h3.x)));
                o.y = fmaf(A0, h0.y, fmaf(A1, h1.y, fmaf(A2, h2.y, A3 * h3.y)));
                o.z = fmaf(A0, h0.z, fmaf(A1, h1.z, fmaf(A2, h2.z, A3 * h3.z)));
                o.w = fmaf(A0, h0.w, fmaf(A1, h1.w, fmaf(A2, h2.w, A3 * h3.w)));
                stcs4(op, o);

                o.x = fmaf(B0, h0.x, fmaf(B1, h1.x, fmaf(B2, h2.x, B3 * h3.x)));
                o.y = fmaf(B0, h0.y, fmaf(B1, h1.y, fmaf(B2, h2.y, B3 * h3.y)));
                o.z = fmaf(B0, h0.z, fmaf(B1, h1.z, fmaf(B2, h2.z, B3 * h3.z)));
                o.w = fmaf(B0, h0.w, fmaf(B1, h1.w, fmaf(B2, h2.w, B3 * h3.w)));
                stcs4(op + OUT_W, o);

                o.x = fmaf(B3, h1.x, fmaf(B2, h2.x, fmaf(B1, h3.x, B0 * h4.x)));
                o.y = fmaf(B3, h1.y, fmaf(B2, h2.y, fmaf(B1, h3.y, B0 * h4.y)));
                o.z = fmaf(B3, h1.z, fmaf(B2, h2.z, fmaf(B1, h3.z, B0 * h4.z)));
                o.w = fmaf(B3, h1.w, fmaf(B2, h2.w, fmaf(B1, h3.w, B0 * h4.w)));
                stcs4(op + 2 * OUT_W, o);

                o.x = fmaf(A3, h1.x, fmaf(A2, h2.x, fmaf(A1, h3.x, A0 * h4.x)));
                o.y = fmaf(A3, h1.y, fmaf(A2, h2.y, fmaf(A1, h3.y, A0 * h4.y)));
                o.z = fmaf(A3, h1.z, fmaf(A2, h2.z, fmaf(A1, h3.z, A0 * h4.z)));
                o.w = fmaf(A3, h1.w, fmaf(A2, h2.w, fmaf(A1, h3.w, A0 * h4.w)));
                stcs4(op + 3 * OUT_W, o);
            } else {
                stcs4(op,             border_dot5_v4(qyg, TA,  h0, h1, h2, h3, h4));
                stcs4(op + OUT_W,     border_dot5_v4(qyg, TB,  h0, h1, h2, h3, h4));
                stcs4(op + 2 * OUT_W, border_dot5_v4(qyg, TBr, h0, h1, h2, h3, h4));
                stcs4(op + 3 * OUT_W, border_dot5_v4(qyg, TAr, h0, h1, h2, h3, h4));
            }

            if (c < 3) {                  // roll the h window
                h0 = h1; h1 = h2; h2 = h3; h3 = h4;
                COMPUTE_H(h4, rb + c + 5);
            }
        }
#undef COMPUTE_H

        // all reads of sin_t for this tile are done before restaging
        __syncthreads();
    }
}

extern "C" void kernel_launch(void* const* d_in, const int* in_sizes, int n_in,
                              void* d_out, int out_size)
{
    const float* x   = (const float*)d_in[0];
    float*       out = (float*)d_out;

    bicubic4x_persist_kernel<<<888, 256>>>(x, out);   // 148 SMs x 6 CTAs
}

// round 14
// speedup vs baseline: 1.1953x; 1.1953x over previous
#include <cuda_runtime.h>
#include <cuda_bf16.h>

// Bicubic x4 upsample, Keys a=-0.5, matching jax.image.resize(method="cubic").
//   input (16,3,256,256) f32 -> output (16,3,1024,1024) f32
// Block = 256 threads, 32x32 input cells -> 128x128 output tile.
//   Phase A: stage 36x36 input halo in smem (coalesced, clamped)
//   Fused:   each thread owns one x-cell column and 4 y-cells; rolling 5-deep
//            float4 h-window in registers; streaming float4 stores (evict-first).
// Borders (edge blocks only) use masked+renormalized weights (jax semantics).
//
// FINAL KERNEL (R7 configuration; benched 34.8/34.9/35.1us).
// Experiment ledger: R6 fusion (neutral), R8 finer tiles (neutral), R9
// full-row write tiles (neutral), R11 256-bit stores (regression), R13
// persistent CTAs (regression) — all confirm this kernel sits on the HBM
// write-stream drain floor for the 192MB fp32 output. Streaming .cs 128-bit
// stores + 6 CTAs/SM + independent-CTA scheduling (cross-CTA stage/store
// overlap) is the optimal configuration found.

#define IN_W   256
#define IN_H   256
#define OUT_W  1024
#define PLANE_IN  (IN_W * IN_H)
#define PLANE_OUT (OUT_W * OUT_W)

#define A0 (-0.0439453125f)
#define A1 ( 0.3896484375f)
#define A2 ( 0.7275390625f)
#define A3 (-0.0732421875f)
#define B0 (-0.0068359375f)
#define B1 ( 0.0908203125f)
#define B2 ( 0.9638671875f)
#define B3 (-0.0478515625f)

// streaming (evict-first) 128-bit store
__device__ __forceinline__ void stcs4(float* p, float4 v) {
    asm volatile("st.global.cs.v4.f32 [%0], {%1,%2,%3,%4};"
                 :: "l"(p), "f"(v.x), "f"(v.y), "f"(v.z), "f"(v.w) : "memory");
}

__device__ __forceinline__ float border_dot5(int q, const float wt[5],
                                             float v0, float v1, float v2,
                                             float v3, float v4)
{
    float w[5]; float s = 0.f;
#pragma unroll
    for (int j = 0; j < 5; j++) {
        int idx = q - 2 + j;
        float ww = (idx >= 0 && idx < IN_W) ? wt[j] : 0.f;
        w[j] = ww; s += ww;
    }
    float inv = 1.0f / s;
    float r = w[0] * v0;
    r = fmaf(w[1], v1, r);
    r = fmaf(w[2], v2, r);
    r = fmaf(w[3], v3, r);
    r = fmaf(w[4], v4, r);
    return r * inv;
}

__device__ __forceinline__ float4 border_dot5_v4(int q, const float wt[5],
                                                 float4 v0, float4 v1, float4 v2,
                                                 float4 v3, float4 v4)
{
    float w[5]; float s = 0.f;
#pragma unroll
    for (int j = 0; j < 5; j++) {
        int idx = q - 2 + j;
        float ww = (idx >= 0 && idx < IN_H) ? wt[j] : 0.f;
        w[j] = ww; s += ww;
    }
    float inv = 1.0f / s;
    float4 o;
    o.x = (fmaf(w[4], v4.x, fmaf(w[3], v3.x, fmaf(w[2], v2.x, fmaf(w[1], v1.x, w[0] * v0.x))))) * inv;
    o.y = (fmaf(w[4], v4.y, fmaf(w[3], v3.y, fmaf(w[2], v2.y, fmaf(w[1], v1.y, w[0] * v0.y))))) * inv;
    o.z = (fmaf(w[4], v4.z, fmaf(w[3], v3.z, fmaf(w[2], v2.z, fmaf(w[1], v1.z, w[0] * v0.z))))) * inv;
    o.w = (fmaf(w[4], v4.w, fmaf(w[3], v3.w, fmaf(w[2], v2.w, fmaf(w[1], v1.w, w[0] * v0.w))))) * inv;
    return o;
}

__global__ void __launch_bounds__(256, 6)
bicubic4x_fused6_kernel(const float* __restrict__ in, float* __restrict__ out)
{
    __shared__ float sin_t[36][40];    // input halo only (5.76 KB)

    const int tid   = threadIdx.x;
    const int qx0   = blockIdx.x * 32;
    const int qy0   = blockIdx.y * 32;
    const int plane = blockIdx.z;

    const bool xedge = (blockIdx.x == 0) | (blockIdx.x == 7);
    const bool yedge = (blockIdx.y == 0) | (blockIdx.y == 7);

    const float* ip = in + (size_t)plane * PLANE_IN;

    static const float TA[5]  = {A0,  A1,  A2,  A3,  0.f};
    static const float TB[5]  = {B0,  B1,  B2,  B3,  0.f};
    static const float TBr[5] = {0.f, B3,  B2,  B1,  B0 };
    static const float TAr[5] = {0.f, A3,  A2,  A1,  A0 };

    // ---------- Phase A: stage 36x36 halo (coalesced, clamped) ----------
#pragma unroll
    for (int i = tid; i < 36 * 36; i += 256) {
        int r = i / 36;
        int c = i - r * 36;
        int gy = qy0 - 2 + r;  gy = gy < 0 ? 0 : (gy > IN_H - 1 ? IN_H - 1 : gy);
        int gx = qx0 - 2 + c;  gx = gx < 0 ? 0 : (gx > IN_W - 1 ? IN_W - 1 : gx);
        sin_t[r][c] = __ldg(ip + gy * IN_W + gx);
    }
    __syncthreads();

    // ---------- Fused horizontal + vertical pass ----------
    const int q   = tid & 31;
    const int ys  = tid >> 5;            // 0..7
    const int qg  = qx0 + q;             // global x cell
    const int rb  = ys * 4;              // first halo row of this strip
    const bool xint = !xedge || (qg >= 2 && qg <= IN_W - 3);

#define COMPUTE_H(dst, rr)                                                      \
    {                                                                           \
        const float* srow = sin_t[rr];                                          \
        float v0 = srow[q + 0], v1 = srow[q + 1], v2 = srow[q + 2],             \
              v3 = srow[q + 3], v4 = srow[q + 4];                               \
        if (xint) {                                                             \
            dst.x = fmaf(A0, v0, fmaf(A1, v1, fmaf(A2, v2, A3 * v3)));          \
            dst.y = fmaf(B0, v0, fmaf(B1, v1, fmaf(B2, v2, B3 * v3)));          \
            dst.z = fmaf(B3, v1, fmaf(B2, v2, fmaf(B1, v3, B0 * v4)));          \
            dst.w = fmaf(A3, v1, fmaf(A2, v2, fmaf(A1, v3, A0 * v4)));          \
        } else {                                                                \
            dst.x = border_dot5(qg, TA,  v0, v1, v2, v3, v4);                   \
            dst.y = border_dot5(qg, TB,  v0, v1, v2, v3, v4);                   \
            dst.z = border_dot5(qg, TBr, v0, v1, v2, v3, v4);                   \
            dst.w = border_dot5(qg, TAr, v0, v1, v2, v3, v4);                   \
        }                                                                       \
    }

    float4 h0, h1, h2, h3, h4;
    COMPUTE_H(h0, rb + 0);
    COMPUTE_H(h1, rb + 1);
    COMPUTE_H(h2, rb + 2);
    COMPUTE_H(h3, rb + 3);
    COMPUTE_H(h4, rb + 4);

    // base output pointer for this thread's first output row
    float* op0 = out + (size_t)plane * PLANE_OUT
                     + (size_t)((qy0 + rb) * 4) * OUT_W
                     + (size_t)(qx0 * 4) + (size_t)q * 4;

#pragma unroll
    for (int c = 0; c < 4; c++) {
        const int qyg = qy0 + rb + c;
        float* op = op0 + (size_t)(c * 4) * OUT_W;

        if (!yedge || (qyg >= 2 && qyg <= IN_H - 3)) {
            float4 o;
            o.x = fmaf(A0, h0.x, fmaf(A1, h1.x, fmaf(A2, h2.x, A3 * h3.x)));
            o.y = fmaf(A0, h0.y, fmaf(A1, h1.y, fmaf(A2, h2.y, A3 * h3.y)));
            o.z = fmaf(A0, h0.z, fmaf(A1, h1.z, fmaf(A2, h2.z, A3 * h3.z)));
            o.w = fmaf(A0, h0.w, fmaf(A1, h1.w, fmaf(A2, h2.w, A3 * h3.w)));
            stcs4(op, o);

            o.x = fmaf(B0, h0.x, fmaf(B1, h1.x, fmaf(B2, h2.x, B3 * h3.x)));
            o.y = fmaf(B0, h0.y, fmaf(B1, h1.y, fmaf(B2, h2.y, B3 * h3.y)));
            o.z = fmaf(B0, h0.z, fmaf(B1, h1.z, fmaf(B2, h2.z, B3 * h3.z)));
            o.w = fmaf(B0, h0.w, fmaf(B1, h1.w, fmaf(B2, h2.w, B3 * h3.w)));
            stcs4(op + OUT_W, o);

            o.x = fmaf(B3, h1.x, fmaf(B2, h2.x, fmaf(B1, h3.x, B0 * h4.x)));
            o.y = fmaf(B3, h1.y, fmaf(B2, h2.y, fmaf(B1, h3.y, B0 * h4.y)));
            o.z = fmaf(B3, h1.z, fmaf(B2, h2.z, fmaf(B1, h3.z, B0 * h4.z)));
            o.w = fmaf(B3, h1.w, fmaf(B2, h2.w, fmaf(B1, h3.w, B0 * h4.w)));
            stcs4(op + 2 * OUT_W, o);

            o.x = fmaf(A3, h1.x, fmaf(A2, h2.x, fmaf(A1, h3.x, A0 * h4.x)));
            o.y = fmaf(A3, h1.y, fmaf(A2, h2.y, fmaf(A1, h3.y, A0 * h4.y)));
            o.z = fmaf(A3, h1.z, fmaf(A2, h2.z, fmaf(A1, h3.z, A0 * h4.z)));
            o.w = fmaf(A3, h1.w, fmaf(A2, h2.w, fmaf(A1, h3.w, A0 * h4.w)));
            stcs4(op + 3 * OUT_W, o);
        } else {
            stcs4(op,             border_dot5_v4(qyg, TA,  h0, h1, h2, h3, h4));
            stcs4(op + OUT_W,     border_dot5_v4(qyg, TB,  h0, h1, h2, h3, h4));
            stcs4(op + 2 * OUT_W, border_dot5_v4(qyg, TBr, h0, h1, h2, h3, h4));
            stcs4(op + 3 * OUT_W, border_dot5_v4(qyg, TAr, h0, h1, h2, h3, h4));
        }

        if (c < 3) {                      // roll the h window
            h0 = h1; h1 = h2; h2 = h3; h3 = h4;
            COMPUTE_H(h4, rb + c + 5);
        }
    }
#undef COMPUTE_H
}

extern "C" void kernel_launch(void* const* d_in, const int* in_sizes, int n_in,
                              void* d_out, int out_size)
{
    const float* x   = (const float*)d_in[0];
    float*       out = (float*)d_out;

    dim3 grid(8, 8, 48);   // 8x8 tiles per plane, 48 planes
    bicubic4x_fused6_kernel<<<grid, 256>>>(x, out);
}

// round 15
// speedup vs baseline: 1.2195x; 1.0202x over previous
#include <cuda_runtime.h>
#include <cuda_bf16.h>

// Bicubic x4 upsample, Keys a=-0.5, matching jax.image.resize(method="cubic").
//   input (16,3,256,256) f32 -> output (16,3,1024,1024) f32
// Block = 256 threads, 32x32 input cells -> 128x128 output tile.
//   Phase A: stage 36x36 input halo in smem (coalesced, clamped)
//   Fused:   each thread owns one x-cell column and 4 y-cells; rolling 5-deep
//            float4 h-window in registers; streaming float4 stores (evict-first).
// Borders (edge blocks only) use masked+renormalized weights (jax semantics).
//
// FINAL KERNEL (R7 configuration; best bench 34.8us, noise band 34.8-35.6).
// Session ledger: R6 fusion (neutral), R8 finer tiles (neutral), R9 full-row
// write tiles (neutral), R11 256-bit stores (regression), R13 persistent CTAs
// (regression). All results consistent with one model: this is a 192MB fp32
// write-stream problem sitting on the HBM write-drain floor (~33-35us).
// Streaming .cs 128-bit stores + 6 CTAs/SM + independent-CTA scheduling
// (cross-CTA stage/store overlap) is the optimal configuration found.

#define IN_W   256
#define IN_H   256
#define OUT_W  1024
#define PLANE_IN  (IN_W * IN_H)
#define PLANE_OUT (OUT_W * OUT_W)

#define A0 (-0.0439453125f)
#define A1 ( 0.3896484375f)
#define A2 ( 0.7275390625f)
#define A3 (-0.0732421875f)
#define B0 (-0.0068359375f)
#define B1 ( 0.0908203125f)
#define B2 ( 0.9638671875f)
#define B3 (-0.0478515625f)

// streaming (evict-first) 128-bit store
__device__ __forceinline__ void stcs4(float* p, float4 v) {
    asm volatile("st.global.cs.v4.f32 [%0], {%1,%2,%3,%4};"
                 :: "l"(p), "f"(v.x), "f"(v.y), "f"(v.z), "f"(v.w) : "memory");
}

__device__ __forceinline__ float border_dot5(int q, const float wt[5],
                                             float v0, float v1, float v2,
                                             float v3, float v4)
{
    float w[5]; float s = 0.f;
#pragma unroll
    for (int j = 0; j < 5; j++) {
        int idx = q - 2 + j;
        float ww = (idx >= 0 && idx < IN_W) ? wt[j] : 0.f;
        w[j] = ww; s += ww;
    }
    float inv = 1.0f / s;
    float r = w[0] * v0;
    r = fmaf(w[1], v1, r);
    r = fmaf(w[2], v2, r);
    r = fmaf(w[3], v3, r);
    r = fmaf(w[4], v4, r);
    return r * inv;
}

__device__ __forceinline__ float4 border_dot5_v4(int q, const float wt[5],
                                                 float4 v0, float4 v1, float4 v2,
                                                 float4 v3, float4 v4)
{
    float w[5]; float s = 0.f;
#pragma unroll
    for (int j = 0; j < 5; j++) {
        int idx = q - 2 + j;
        float ww = (idx >= 0 && idx < IN_H) ? wt[j] : 0.f;
        w[j] = ww; s += ww;
    }
    float inv = 1.0f / s;
    float4 o;
    o.x = (fmaf(w[4], v4.x, fmaf(w[3], v3.x, fmaf(w[2], v2.x, fmaf(w[1], v1.x, w[0] * v0.x))))) * inv;
    o.y = (fmaf(w[4], v4.y, fmaf(w[3], v3.y, fmaf(w[2], v2.y, fmaf(w[1], v1.y, w[0] * v0.y))))) * inv;
    o.z = (fmaf(w[4], v4.z, fmaf(w[3], v3.z, fmaf(w[2], v2.z, fmaf(w[1], v1.z, w[0] * v0.z))))) * inv;
    o.w = (fmaf(w[4], v4.w, fmaf(w[3], v3.w, fmaf(w[2], v2.w, fmaf(w[1], v1.w, w[0] * v0.w))))) * inv;
    return o;
}

__global__ void __launch_bounds__(256, 6)
bicubic4x_fused6_kernel(const float* __restrict__ in, float* __restrict__ out)
{
    __shared__ float sin_t[36][40];    // input halo only (5.76 KB)

    const int tid   = threadIdx.x;
    const int qx0   = blockIdx.x * 32;
    const int qy0   = blockIdx.y * 32;
    const int plane = blockIdx.z;

    const bool xedge = (blockIdx.x == 0) | (blockIdx.x == 7);
    const bool yedge = (blockIdx.y == 0) | (blockIdx.y == 7);

    const float* ip = in + (size_t)plane * PLANE_IN;

    static const float TA[5]  = {A0,  A1,  A2,  A3,  0.f};
    static const float TB[5]  = {B0,  B1,  B2,  B3,  0.f};
    static const float TBr[5] = {0.f, B3,  B2,  B1,  B0 };
    static const float TAr[5] = {0.f, A3,  A2,  A1,  A0 };

    // ---------- Phase A: stage 36x36 halo (coalesced, clamped) ----------
#pragma unroll
    for (int i = tid; i < 36 * 36; i += 256) {
        int r = i / 36;
        int c = i - r * 36;
        int gy = qy0 - 2 + r;  gy = gy < 0 ? 0 : (gy > IN_H - 1 ? IN_H - 1 : gy);
        int gx = qx0 - 2 + c;  gx = gx < 0 ? 0 : (gx > IN_W - 1 ? IN_W - 1 : gx);
        sin_t[r][c] = __ldg(ip + gy * IN_W + gx);
    }
    __syncthreads();

    // ---------- Fused horizontal + vertical pass ----------
    const int q   = tid & 31;
    const int ys  = tid >> 5;            // 0..7
    const int qg  = qx0 + q;             // global x cell
    const int rb  = ys * 4;              // first halo row of this strip
    const bool xint = !xedge || (qg >= 2 && qg <= IN_W - 3);

#define COMPUTE_H(dst, rr)                                                      \
    {                                                                           \
        const float* srow = sin_t[rr];                                          \
        float v0 = srow[q + 0], v1 = srow[q + 1], v2 = srow[q + 2],             \
              v3 = srow[q + 3], v4 = srow[q + 4];                               \
        if (xint) {                                                             \
            dst.x = fmaf(A0, v0, fmaf(A1, v1, fmaf(A2, v2, A3 * v3)));          \
            dst.y = fmaf(B0, v0, fmaf(B1, v1, fmaf(B2, v2, B3 * v3)));          \
            dst.z = fmaf(B3, v1, fmaf(B2, v2, fmaf(B1, v3, B0 * v4)));          \
            dst.w = fmaf(A3, v1, fmaf(A2, v2, fmaf(A1, v3, A0 * v4)));          \
        } else {                                                                \
            dst.x = border_dot5(qg, TA,  v0, v1, v2, v3, v4);                   \
            dst.y = border_dot5(qg, TB,  v0, v1, v2, v3, v4);                   \
            dst.z = border_dot5(qg, TBr, v0, v1, v2, v3, v4);                   \
            dst.w = border_dot5(qg, TAr, v0, v1, v2, v3, v4);                   \
        }                                                                       \
    }

    float4 h0, h1, h2, h3, h4;
    COMPUTE_H(h0, rb + 0);
    COMPUTE_H(h1, rb + 1);
    COMPUTE_H(h2, rb + 2);
    COMPUTE_H(h3, rb + 3);
    COMPUTE_H(h4, rb + 4);

    // base output pointer for this thread's first output row
    float* op0 = out + (size_t)plane * PLANE_OUT
                     + (size_t)((qy0 + rb) * 4) * OUT_W
                     + (size_t)(qx0 * 4) + (size_t)q * 4;

#pragma unroll
    for (int c = 0; c < 4; c++) {
        const int qyg = qy0 + rb + c;
        float* op = op0 + (size_t)(c * 4) * OUT_W;

        if (!yedge || (qyg >= 2 && qyg <= IN_H - 3)) {
            float4 o;
            o.x = fmaf(A0, h0.x, fmaf(A1, h1.x, fmaf(A2, h2.x, A3 * h3.x)));
            o.y = fmaf(A0, h0.y, fmaf(A1, h1.y, fmaf(A2, h2.y, A3 * h3.y)));
            o.z = fmaf(A0, h0.z, fmaf(A1, h1.z, fmaf(A2, h2.z, A3 * h3.z)));
            o.w = fmaf(A0, h0.w, fmaf(A1, h1.w, fmaf(A2, h2.w, A3 * h3.w)));
            stcs4(op, o);

            o.x = fmaf(B0, h0.x, fmaf(B1, h1.x, fmaf(B2, h2.x, B3 * h3.x)));
            o.y = fmaf(B0, h0.y, fmaf(B1, h1.y, fmaf(B2, h2.y, B3 * h3.y)));
            o.z = fmaf(B0, h0.z, fmaf(B1, h1.z, fmaf(B2, h2.z, B3 * h3.z)));
            o.w = fmaf(B0, h0.w, fmaf(B1, h1.w, fmaf(B2, h2.w, B3 * h3.w)));
            stcs4(op + OUT_W, o);

            o.x = fmaf(B3, h1.x, fmaf(B2, h2.x, fmaf(B1, h3.x, B0 * h4.x)));
            o.y = fmaf(B3, h1.y, fmaf(B2, h2.y, fmaf(B1, h3.y, B0 * h4.y)));
            o.z = fmaf(B3, h1.z, fmaf(B2, h2.z, fmaf(B1, h3.z, B0 * h4.z)));
            o.w = fmaf(B3, h1.w, fmaf(B2, h2.w, fmaf(B1, h3.w, B0 * h4.w)));
            stcs4(op + 2 * OUT_W, o);

            o.x = fmaf(A3, h1.x, fmaf(A2, h2.x, fmaf(A1, h3.x, A0 * h4.x)));
            o.y = fmaf(A3, h1.y, fmaf(A2, h2.y, fmaf(A1, h3.y, A0 * h4.y)));
            o.z = fmaf(A3, h1.z, fmaf(A2, h2.z, fmaf(A1, h3.z, A0 * h4.z)));
            o.w = fmaf(A3, h1.w, fmaf(A2, h2.w, fmaf(A1, h3.w, A0 * h4.w)));
            stcs4(op + 3 * OUT_W, o);
        } else {
            stcs4(op,             border_dot5_v4(qyg, TA,  h0, h1, h2, h3, h4));
            stcs4(op + OUT_W,     border_dot5_v4(qyg, TB,  h0, h1, h2, h3, h4));
            stcs4(op + 2 * OUT_W, border_dot5_v4(qyg, TBr, h0, h1, h2, h3, h4));
            stcs4(op + 3 * OUT_W, border_dot5_v4(qyg, TAr, h0, h1, h2, h3, h4));
        }

        if (c < 3) {                      // roll the h window
            h0 = h1; h1 = h2; h2 = h3; h3 = h4;
            COMPUTE_H(h4, rb + c + 5);
        }
    }
#undef COMPUTE_H
}

extern "C" void kernel_launch(void* const* d_in, const int* in_sizes, int n_in,
                              void* d_out, int out_size)
{
    const float* x   = (const float*)d_in[0];
    float*       out = (float*)d_out;

    dim3 grid(8, 8, 48);   // 8x8 tiles per plane, 48 planes
    bicubic4x_fused6_kernel<<<grid, 256>>>(x, out);
}